// round 7
// baseline (speedup 1.0000x reference)
#include <cuda_runtime.h>

#define EMB 64
#define NL_MAX 50000
#define NR_MAX 100000
#define NE_MAX 1000000
#define BN_EPS 1e-5f

#define WPAD 68         // wsT row pad: rows 16B-aligned (68*4=272)
#define TROWS 96        // rows per block tile
#define RPTN 6          // rows per thread (16 row-groups x 6)

typedef unsigned long long u64;

__device__ __forceinline__ u64 pack2(float lo, float hi) {
    u64 r; asm("mov.b64 %0, {%1,%2};" : "=l"(r) : "f"(lo), "f"(hi)); return r;
}
__device__ __forceinline__ void fma2(u64& acc, u64 a, u64 b) {
    asm("fma.rn.f32x2 %0, %1, %2, %0;" : "+l"(acc) : "l"(a), "l"(b));
}
__device__ __forceinline__ float2 unpack2(u64 v) {
    float2 f; asm("mov.b64 {%0,%1}, %2;" : "=f"(f.x), "=f"(f.y) : "l"(v)); return f;
}

// ---------------- scratch (static device globals) ----------------------------
__device__ float d_LP[NL_MAX * EMB];
__device__ float d_RP[NR_MAX * EMB];
__device__ float d_S[NR_MAX * EMB];
__device__ float d_conv[NR_MAX * EMB];
__device__ float d_deg[NR_MAX];
__device__ float d_stats[256];   // [0:64) sum1, [64:128) sq1, [128:192) sum2, [192:256) sq2
__device__ float d_sc[256];      // [0:64) scale1, [64:128) shift1, [128:192) scale2, [192:256) shift2

// ---------------- zero scratch (vectorized) ----------------------------------
__global__ void zero_kernel(int nS4, int nR) {
    int i = blockIdx.x * blockDim.x + threadIdx.x;
    if (i < nS4) ((float4*)d_S)[i] = make_float4(0.f, 0.f, 0.f, 0.f);
    if (i < nR) d_deg[i] = 0.f;
    if (i < 256) d_stats[i] = 0.f;
}

// ---------------- staging helpers --------------------------------------------
__device__ __forceinline__ void stage_w64(const float* __restrict__ W,
                                          float (*wsT)[WPAD], int t, int rowstride) {
#pragma unroll
    for (int p = 0; p < 4; p++) {
        int i = t + p * 256;
        int c = i >> 4;
        int k4 = (i & 15) * 4;
        float4 w4 = *(const float4*)&W[c * rowstride + k4];
        wsT[k4 + 0][c] = w4.x;
        wsT[k4 + 1][c] = w4.y;
        wsT[k4 + 2][c] = w4.z;
        wsT[k4 + 3][c] = w4.w;
    }
}

// ---------------- generic 64-wide GEMM (FFMA2 packed) ------------------------
// MODE 0: out = X@W.T ; 1: +bias ; 2: +deg*bias & bn2 stats ; 3: relu(+bias)
// 256 thr: cg=t&15 owns cols 4cg..4cg+3 (two packed pairs); rg=t>>4 owns 6 rows.
template <int MODE>
__global__ __launch_bounds__(256) void gemm64_kernel(
    const float* __restrict__ X, const float* __restrict__ W,
    const float* __restrict__ bias, const float* __restrict__ deg,
    float* __restrict__ out, int nrows)
{
    __shared__ float xs[TROWS][EMB];
    __shared__ float wsT[EMB][WPAD];
    __shared__ float red[128];

    int t = threadIdx.x;
    int cg = t & 15;
    int rg = t >> 4;
    int row0 = blockIdx.x * TROWS;
    int ca = 4 * cg;
    int r0 = rg * RPTN;

    stage_w64(W, wsT, t, EMB);
#pragma unroll
    for (int p = 0; p < TROWS / 16; p++) {
        int i = t + p * 256;
        int r = i >> 4;
        int c4 = (i & 15) * 4;
        int gr = row0 + r;
        float4 v = (gr < nrows) ? *(const float4*)&X[gr * EMB + c4]
                                : make_float4(0.f, 0.f, 0.f, 0.f);
        *(float4*)&xs[r][c4] = v;
    }
    __syncthreads();

    u64 acc0[RPTN], acc1[RPTN];
    if (MODE == 0) {
#pragma unroll
        for (int j = 0; j < RPTN; j++) { acc0[j] = pack2(0.f, 0.f); acc1[j] = pack2(0.f, 0.f); }
    } else if (MODE == 1 || MODE == 3) {
        u64 b01 = pack2(bias[ca], bias[ca + 1]);
        u64 b23 = pack2(bias[ca + 2], bias[ca + 3]);
#pragma unroll
        for (int j = 0; j < RPTN; j++) { acc0[j] = b01; acc1[j] = b23; }
    } else { // MODE 2
        float b0 = bias[ca], b1v = bias[ca + 1], b2v = bias[ca + 2], b3v = bias[ca + 3];
#pragma unroll
        for (int j = 0; j < RPTN; j++) {
            int gr = row0 + r0 + j;
            float dv = (gr < nrows) ? deg[gr] : 0.f;
            acc0[j] = pack2(dv * b0, dv * b1v);
            acc1[j] = pack2(dv * b2v, dv * b3v);
        }
    }

#pragma unroll
    for (int kq = 0; kq < 16; kq++) {
        int k = 4 * kq;
        ulonglong2 w0 = *(const ulonglong2*)&wsT[k + 0][ca];
        ulonglong2 w1 = *(const ulonglong2*)&wsT[k + 1][ca];
        ulonglong2 w2 = *(const ulonglong2*)&wsT[k + 2][ca];
        ulonglong2 w3 = *(const ulonglong2*)&wsT[k + 3][ca];
#pragma unroll
        for (int j = 0; j < RPTN; j++) {
            float4 x4 = *(const float4*)&xs[r0 + j][k];
            u64 xx;
            xx = pack2(x4.x, x4.x); fma2(acc0[j], xx, w0.x); fma2(acc1[j], xx, w0.y);
            xx = pack2(x4.y, x4.y); fma2(acc0[j], xx, w1.x); fma2(acc1[j], xx, w1.y);
            xx = pack2(x4.z, x4.z); fma2(acc0[j], xx, w2.x); fma2(acc1[j], xx, w2.y);
            xx = pack2(x4.w, x4.w); fma2(acc0[j], xx, w3.x); fma2(acc1[j], xx, w3.y);
        }
    }

    float s0 = 0.f, s1 = 0.f, s2 = 0.f, s3 = 0.f;
    float q0 = 0.f, q1 = 0.f, q2 = 0.f, q3 = 0.f;
#pragma unroll
    for (int j = 0; j < RPTN; j++) {
        int gr = row0 + r0 + j;
        if (gr < nrows) {
            float2 v01 = unpack2(acc0[j]);
            float2 v23 = unpack2(acc1[j]);
            if (MODE == 3) {
                v01.x = fmaxf(v01.x, 0.f); v01.y = fmaxf(v01.y, 0.f);
                v23.x = fmaxf(v23.x, 0.f); v23.y = fmaxf(v23.y, 0.f);
            }
            *(float4*)&out[gr * EMB + ca] = make_float4(v01.x, v01.y, v23.x, v23.y);
            if (MODE == 2) {
                s0 += v01.x; q0 += v01.x * v01.x;
                s1 += v01.y; q1 += v01.y * v01.y;
                s2 += v23.x; q2 += v23.x * v23.x;
                s3 += v23.y; q3 += v23.y * v23.y;
            }
        }
    }

    if (MODE == 2) {
        if (t < 128) red[t] = 0.f;
        __syncthreads();
        atomicAdd(&red[ca + 0], s0);
        atomicAdd(&red[ca + 1], s1);
        atomicAdd(&red[ca + 2], s2);
        atomicAdd(&red[ca + 3], s3);
        atomicAdd(&red[64 + ca + 0], q0);
        atomicAdd(&red[64 + ca + 1], q1);
        atomicAdd(&red[64 + ca + 2], q2);
        atomicAdd(&red[64 + ca + 3], q3);
        __syncthreads();
        if (t < 128) atomicAdd(&d_stats[128 + t], red[t]);
    }
}

// ---------------- edge pass 1: bn1 stats + degree (ILP x2, 192-thr blocks) --
__global__ __launch_bounds__(192) void edge_stats_kernel(
    const int* __restrict__ ei, const float* __restrict__ ef,
    const float* __restrict__ Wedge, int NE)
{
    int t = threadIdx.x;
    int g = t & 15;
    int slot = blockIdx.x * 12 + (t >> 4);
    int step = gridDim.x * 12;
    float4 we = ((const float4*)Wedge)[g];
    float4 sum = make_float4(0.f, 0.f, 0.f, 0.f);
    float4 sq = make_float4(0.f, 0.f, 0.f, 0.f);

    for (int e = slot; e < NE; e += 2 * step) {
        int eB = e + step;
        bool hasB = eB < NE;
        int eBc = hasB ? eB : e;
        int i0a = ei[e];
        int i1a = ei[NE + e];
        float fa = ef[e];
        int i0b = ei[eBc];
        int i1b = ei[NE + eBc];
        float fb = ef[eBc];
        float4 lpA = ((const float4*)d_LP)[i0a * 16 + g];
        float4 rpA = ((const float4*)d_RP)[i1a * 16 + g];
        float4 lpB = ((const float4*)d_LP)[i0b * 16 + g];
        float4 rpB = ((const float4*)d_RP)[i1b * 16 + g];

        float4 jA;
        jA.x = fmaf(fa, we.x, lpA.x + rpA.x);
        jA.y = fmaf(fa, we.y, lpA.y + rpA.y);
        jA.z = fmaf(fa, we.z, lpA.z + rpA.z);
        jA.w = fmaf(fa, we.w, lpA.w + rpA.w);
        sum.x += jA.x; sum.y += jA.y; sum.z += jA.z; sum.w += jA.w;
        sq.x += jA.x * jA.x; sq.y += jA.y * jA.y;
        sq.z += jA.z * jA.z; sq.w += jA.w * jA.w;

        float m = hasB ? 1.f : 0.f;
        float4 jB;
        jB.x = fmaf(fb, we.x, lpB.x + rpB.x);
        jB.y = fmaf(fb, we.y, lpB.y + rpB.y);
        jB.z = fmaf(fb, we.z, lpB.z + rpB.z);
        jB.w = fmaf(fb, we.w, lpB.w + rpB.w);
        sum.x += m * jB.x; sum.y += m * jB.y;
        sum.z += m * jB.z; sum.w += m * jB.w;
        sq.x += m * jB.x * jB.x; sq.y += m * jB.y * jB.y;
        sq.z += m * jB.z * jB.z; sq.w += m * jB.w * jB.w;

        if (g == 0) {
            atomicAdd(&d_deg[i1a], 1.f);
            if (hasB) atomicAdd(&d_deg[i1b], 1.f);
        }
    }

    __shared__ float red[128];
    if (t < 128) red[t] = 0.f;
    __syncthreads();
    atomicAdd(&red[4 * g + 0], sum.x);
    atomicAdd(&red[4 * g + 1], sum.y);
    atomicAdd(&red[4 * g + 2], sum.z);
    atomicAdd(&red[4 * g + 3], sum.w);
    atomicAdd(&red[64 + 4 * g + 0], sq.x);
    atomicAdd(&red[64 + 4 * g + 1], sq.y);
    atomicAdd(&red[64 + 4 * g + 2], sq.z);
    atomicAdd(&red[64 + 4 * g + 3], sq.w);
    __syncthreads();
    if (t < 128) atomicAdd(&d_stats[t], red[t]);
}

// ---------------- batchnorm finalize ----------------------------------------
__global__ void bn_finalize_kernel(const float* __restrict__ gamma,
                                   const float* __restrict__ beta,
                                   float cnt, int soff, int ooff)
{
    int c = threadIdx.x;
    if (c < 64) {
        float mean = d_stats[soff + c] / cnt;
        float var = d_stats[soff + 64 + c] / cnt - mean * mean;
        float sc = gamma[c] * rsqrtf(var + BN_EPS);
        d_sc[ooff + c] = sc;
        d_sc[ooff + 64 + c] = beta[c] - mean * sc;
    }
}

// ---------------- edge pass 2: bn1+relu joint, scatter into S (ILP x2) ------
__global__ __launch_bounds__(192) void edge_scatter_kernel(
    const int* __restrict__ ei, const float* __restrict__ ef,
    const float* __restrict__ Wedge, int NE)
{
    int tid = blockIdx.x * 192 + threadIdx.x;
    int p = tid >> 4;
    int g = tid & 15;
    int eA = 2 * p;
    if (eA >= NE) return;
    int eB = eA + 1;
    bool hasB = eB < NE;
    int eBc = hasB ? eB : eA;

    float4 we = ((const float4*)Wedge)[g];
    float4 s = ((const float4*)d_sc)[g];
    float4 sh = ((const float4*)d_sc)[16 + g];

    int i0a = ei[eA];
    int i1a = ei[NE + eA];
    float fa = ef[eA];
    int i0b = ei[eBc];
    int i1b = ei[NE + eBc];
    float fb = ef[eBc];
    float4 lpA = ((const float4*)d_LP)[i0a * 16 + g];
    float4 rpA = ((const float4*)d_RP)[i1a * 16 + g];
    float4 lpB = ((const float4*)d_LP)[i0b * 16 + g];
    float4 rpB = ((const float4*)d_RP)[i1b * 16 + g];

    float4 vA;
    vA.x = fmaxf(fmaf(fmaf(fa, we.x, lpA.x + rpA.x), s.x, sh.x), 0.f);
    vA.y = fmaxf(fmaf(fmaf(fa, we.y, lpA.y + rpA.y), s.y, sh.y), 0.f);
    vA.z = fmaxf(fmaf(fmaf(fa, we.z, lpA.z + rpA.z), s.z, sh.z), 0.f);
    vA.w = fmaxf(fmaf(fmaf(fa, we.w, lpA.w + rpA.w), s.w, sh.w), 0.f);
    float* pa = &d_S[i1a * EMB + 4 * g];
    asm volatile("red.global.add.v4.f32 [%0], {%1,%2,%3,%4};"
                 :: "l"(pa), "f"(vA.x), "f"(vA.y), "f"(vA.z), "f"(vA.w) : "memory");

    if (hasB) {
        float4 vB;
        vB.x = fmaxf(fmaf(fmaf(fb, we.x, lpB.x + rpB.x), s.x, sh.x), 0.f);
        vB.y = fmaxf(fmaf(fmaf(fb, we.y, lpB.y + rpB.y), s.y, sh.y), 0.f);
        vB.z = fmaxf(fmaf(fmaf(fb, we.z, lpB.z + rpB.z), s.z, sh.z), 0.f);
        vB.w = fmaxf(fmaf(fmaf(fb, we.w, lpB.w + rpB.w), s.w, sh.w), 0.f);
        float* pb = &d_S[i1b * EMB + 4 * g];
        asm volatile("red.global.add.v4.f32 [%0], {%1,%2,%3,%4};"
                     :: "l"(pb), "f"(vB.x), "f"(vB.y), "f"(vB.z), "f"(vB.w) : "memory");
    }
}

// ---------------- fused output layers (FFMA2 packed) -------------------------
__global__ __launch_bounds__(256) void out_fused_kernel(
    const float* __restrict__ conv, const float* __restrict__ right,
    const float* __restrict__ W1, const float* __restrict__ b1,
    const float* __restrict__ W2, const float* __restrict__ b2,
    float* __restrict__ out, int nrows)
{
    __shared__ float xs[TROWS][EMB];
    __shared__ float wsT[EMB][WPAD];

    int t = threadIdx.x;
    int cg = t & 15;
    int rg = t >> 4;
    int row0 = blockIdx.x * TROWS;
    int ca = 4 * cg;
    int r0 = rg * RPTN;

    u64 acc0[RPTN], acc1[RPTN];
    {
        u64 b01 = pack2(b1[ca], b1[ca + 1]);
        u64 b23 = pack2(b1[ca + 2], b1[ca + 3]);
#pragma unroll
        for (int j = 0; j < RPTN; j++) { acc0[j] = b01; acc1[j] = b23; }
    }

#pragma unroll
    for (int phase = 0; phase < 2; phase++) {
        int koff = phase * 64;
#pragma unroll
        for (int p = 0; p < 4; p++) {
            int i = t + p * 256;
            int c = i >> 4;
            int k4 = (i & 15) * 4;
            float4 w4 = *(const float4*)&W1[c * 128 + koff + k4];
            wsT[k4 + 0][c] = w4.x;
            wsT[k4 + 1][c] = w4.y;
            wsT[k4 + 2][c] = w4.z;
            wsT[k4 + 3][c] = w4.w;
        }
#pragma unroll
        for (int p = 0; p < TROWS / 16; p++) {
            int i = t + p * 256;
            int r = i >> 4;
            int c4 = (i & 15) * 4;
            int gr = row0 + r;
            float4 v;
            if (gr < nrows) {
                if (phase == 0) {
                    v = *(const float4*)&conv[gr * EMB + c4];
                    v.x = v.x * d_sc[128 + c4 + 0] + d_sc[192 + c4 + 0];
                    v.y = v.y * d_sc[128 + c4 + 1] + d_sc[192 + c4 + 1];
                    v.z = v.z * d_sc[128 + c4 + 2] + d_sc[192 + c4 + 2];
                    v.w = v.w * d_sc[128 + c4 + 3] + d_sc[192 + c4 + 3];
                } else {
                    v = *(const float4*)&right[gr * EMB + c4];
                }
            } else {
                v = make_float4(0.f, 0.f, 0.f, 0.f);
            }
            *(float4*)&xs[r][c4] = v;
        }
        __syncthreads();

#pragma unroll
        for (int kq = 0; kq < 16; kq++) {
            int k = 4 * kq;
            ulonglong2 w0 = *(const ulonglong2*)&wsT[k + 0][ca];
            ulonglong2 w1 = *(const ulonglong2*)&wsT[k + 1][ca];
            ulonglong2 w2 = *(const ulonglong2*)&wsT[k + 2][ca];
            ulonglong2 w3 = *(const ulonglong2*)&wsT[k + 3][ca];
#pragma unroll
            for (int j = 0; j < RPTN; j++) {
                float4 x4 = *(const float4*)&xs[r0 + j][k];
                u64 xx;
                xx = pack2(x4.x, x4.x); fma2(acc0[j], xx, w0.x); fma2(acc1[j], xx, w0.y);
                xx = pack2(x4.y, x4.y); fma2(acc0[j], xx, w1.x); fma2(acc1[j], xx, w1.y);
                xx = pack2(x4.z, x4.z); fma2(acc0[j], xx, w2.x); fma2(acc1[j], xx, w2.y);
                xx = pack2(x4.w, x4.w); fma2(acc0[j], xx, w3.x); fma2(acc1[j], xx, w3.y);
            }
        }
        __syncthreads();
    }

    // h = relu(acc) -> xs ; stage W2 ; second GEMM in-block
#pragma unroll
    for (int j = 0; j < RPTN; j++) {
        float2 v01 = unpack2(acc0[j]);
        float2 v23 = unpack2(acc1[j]);
        *(float4*)&xs[r0 + j][ca] = make_float4(fmaxf(v01.x, 0.f), fmaxf(v01.y, 0.f),
                                                fmaxf(v23.x, 0.f), fmaxf(v23.y, 0.f));
    }
    stage_w64(W2, wsT, t, EMB);
    __syncthreads();

    u64 o0[RPTN], o1[RPTN];
    {
        u64 b01 = pack2(b2[ca], b2[ca + 1]);
        u64 b23 = pack2(b2[ca + 2], b2[ca + 3]);
#pragma unroll
        for (int j = 0; j < RPTN; j++) { o0[j] = b01; o1[j] = b23; }
    }

#pragma unroll
    for (int kq = 0; kq < 16; kq++) {
        int k = 4 * kq;
        ulonglong2 w0 = *(const ulonglong2*)&wsT[k + 0][ca];
        ulonglong2 w1 = *(const ulonglong2*)&wsT[k + 1][ca];
        ulonglong2 w2 = *(const ulonglong2*)&wsT[k + 2][ca];
        ulonglong2 w3 = *(const ulonglong2*)&wsT[k + 3][ca];
#pragma unroll
        for (int j = 0; j < RPTN; j++) {
            float4 x4 = *(const float4*)&xs[r0 + j][k];
            u64 xx;
            xx = pack2(x4.x, x4.x); fma2(o0[j], xx, w0.x); fma2(o1[j], xx, w0.y);
            xx = pack2(x4.y, x4.y); fma2(o0[j], xx, w1.x); fma2(o1[j], xx, w1.y);
            xx = pack2(x4.z, x4.z); fma2(o0[j], xx, w2.x); fma2(o1[j], xx, w2.y);
            xx = pack2(x4.w, x4.w); fma2(o0[j], xx, w3.x); fma2(o1[j], xx, w3.y);
        }
    }

#pragma unroll
    for (int j = 0; j < RPTN; j++) {
        int gr = row0 + r0 + j;
        if (gr < nrows) {
            float2 v01 = unpack2(o0[j]);
            float2 v23 = unpack2(o1[j]);
            *(float4*)&out[gr * EMB + ca] = make_float4(fmaxf(v01.x, 0.f), fmaxf(v01.y, 0.f),
                                                        fmaxf(v23.x, 0.f), fmaxf(v23.y, 0.f));
        }
    }
}

// ---------------- launch -----------------------------------------------------
extern "C" void kernel_launch(void* const* d_in, const int* in_sizes, int n_in,
                              void* d_out, int out_size)
{
    (void)n_in; (void)out_size;
    const float* left   = (const float*)d_in[0];
    const int*   ei     = (const int*)d_in[1];
    const float* ef     = (const float*)d_in[2];
    const float* right  = (const float*)d_in[3];
    const float* W_left  = (const float*)d_in[5];
    const float* b_left  = (const float*)d_in[6];
    const float* W_edge  = (const float*)d_in[7];
    const float* W_right = (const float*)d_in[8];
    const float* g1      = (const float*)d_in[9];
    const float* bt1     = (const float*)d_in[10];
    const float* W_final = (const float*)d_in[11];
    const float* b_final = (const float*)d_in[12];
    const float* g2      = (const float*)d_in[13];
    const float* bt2     = (const float*)d_in[14];
    const float* W1      = (const float*)d_in[15];
    const float* b1      = (const float*)d_in[16];
    const float* W2      = (const float*)d_in[17];
    const float* b2      = (const float*)d_in[18];
    float* out = (float*)d_out;

    int NL = in_sizes[0] / EMB;
    int NE = in_sizes[2];
    int NR = in_sizes[3] / EMB;

    float *pLP, *pRP, *pS, *pConv, *pDeg;
    cudaGetSymbolAddress((void**)&pLP, d_LP);
    cudaGetSymbolAddress((void**)&pRP, d_RP);
    cudaGetSymbolAddress((void**)&pS, d_S);
    cudaGetSymbolAddress((void**)&pConv, d_conv);
    cudaGetSymbolAddress((void**)&pDeg, d_deg);

    int nS4 = NR * EMB / 4;
    zero_kernel<<<(nS4 + 255) / 256, 256>>>(nS4, NR);
    gemm64_kernel<1><<<(NL + TROWS - 1) / TROWS, 256>>>(left, W_left, b_left, nullptr, pLP, NL);
    gemm64_kernel<0><<<(NR + TROWS - 1) / TROWS, 256>>>(right, W_right, nullptr, nullptr, pRP, NR);
    edge_stats_kernel<<<1184, 192>>>(ei, ef, W_edge, NE);
    bn_finalize_kernel<<<1, 64>>>(g1, bt1, (float)NE, 0, 0);
    {
        int npairs = (NE + 1) / 2;
        int nthr = npairs * 16;
        edge_scatter_kernel<<<(nthr + 191) / 192, 192>>>(ei, ef, W_edge, NE);
    }
    gemm64_kernel<2><<<(NR + TROWS - 1) / TROWS, 256>>>(pS, W_final, b_final, pDeg, pConv, NR);
    bn_finalize_kernel<<<1, 64>>>(g2, bt2, (float)NR, 128, 128);
    out_fused_kernel<<<(NR + TROWS - 1) / TROWS, 256>>>(pConv, right, W1, b1, W2, b2, out, NR);
}